// round 5
// baseline (speedup 1.0000x reference)
#include <cuda_runtime.h>
#include <cstdint>

// Problem constants
#define BB 64      // batch
#define KK 4096    // dim_in
#define OO 4096    // dim_out
#define KW 128     // KK/32 bit-words along k
#define OT 32      // output columns per block

// x bits, transposed for lane-coalesced reads in the main kernel: [kw][b]
__device__ uint32_t g_xbitsT[KW * BB];   // 32 KB

// Robust 0/1 extraction from a 32-bit word holding either int32 {0,1}
// (bit 0) or float32 {0.0f,1.0f} (bit 23). For both encodings exactly one
// of bit0/bit23 is set iff value==1.
__device__ __forceinline__ uint32_t bit01(uint32_t w) {
    return (w | (w >> 23)) & 1u;
}

// ---------------------------------------------------------------------------
// Pack x (int32/float32 0/1 words) into bit-words. 8192 threads: one each.
// Word (kw, b) holds bits k = kw*32 .. kw*32+31 of batch row b.
// ---------------------------------------------------------------------------
__global__ void pack_x_kernel(const uint32_t* __restrict__ x) {
    int t  = blockIdx.x * blockDim.x + threadIdx.x;   // 0..8191
    int kw = t >> 6;
    int b  = t & 63;
    const uint4* p = reinterpret_cast<const uint4*>(x + (size_t)b * KK + kw * 32);
    uint32_t w = 0;
    #pragma unroll
    for (int i = 0; i < 8; i++) {
        uint4 v = p[i];
        w |= bit01(v.x) << (4 * i);
        w |= bit01(v.y) << (4 * i + 1);
        w |= bit01(v.z) << (4 * i + 2);
        w |= bit01(v.w) << (4 * i + 3);
    }
    g_xbitsT[kw * BB + b] = w;
}

// ---------------------------------------------------------------------------
// Fused kernel: per block (32 output columns):
//   phase 1: read mask strip [4096 k][32 o] words, bit-pack into shared [kw][o]
//   phase 2: XNOR-popcount vs x bits (lanes = batch), fused threshold epilogue
// ---------------------------------------------------------------------------
__global__ void __launch_bounds__(256, 1) xnor_main_kernel(
    const uint32_t* __restrict__ masks,  // [KK][OO] int32/float32 0/1
    const int*      __restrict__ thr,    // [OO] int32
    float*          __restrict__ out)    // [BB][OO] float32 0/1
{
    __shared__ uint32_t sh_m[KW * OT];   // 16 KB, layout [kw][o]

    const int t  = threadIdx.x;
    const int o0 = blockIdx.x * OT;

    // ---------------- phase 1: pack mask column strip into shared bits -----
    // thread -> (og = column quad 0..7, kwb = 0..31); handles kw = kwb + 32*r
    {
        const int og  = t & 7;
        const int kwb = t >> 3;
        #pragma unroll
        for (int r = 0; r < 4; r++) {
            const int kw = kwb + 32 * r;
            uint32_t a0 = 0, a1 = 0, a2 = 0, a3 = 0;
            const uint4* base = reinterpret_cast<const uint4*>(
                masks + (size_t)(kw * 32) * OO + o0 + og * 4);
            #pragma unroll
            for (int j = 0; j < 32; j++) {
                // row kw*32+j, columns o0+og*4 .. +3 (16B coalesced)
                uint4 m = base[(size_t)j * (OO / 4)];
                a0 |= bit01(m.x) << j;
                a1 |= bit01(m.y) << j;
                a2 |= bit01(m.z) << j;
                a3 |= bit01(m.w) << j;
            }
            // sh_m[kw][4*og .. 4*og+3], 16B vector store
            reinterpret_cast<uint4*>(sh_m)[kw * 8 + og] = make_uint4(a0, a1, a2, a3);
        }
    }
    __syncthreads();

    // ---------------- phase 2: XNOR popcount main loop ----------------------
    const int lane = t & 31;
    const int warp = t >> 5;
    const int half = warp & 1;        // which 32 batches
    const int oset = warp >> 1;       // 0..3 -> 8 columns each
    const int b    = half * 32 + lane;

    int acc[8] = {0, 0, 0, 0, 0, 0, 0, 0};
    const uint4* shm4 = reinterpret_cast<const uint4*>(sh_m);

    #pragma unroll
    for (int ck = 0; ck < 4; ck++) {
        // x bit-words for this chunk, lane-coalesced (lanes = consecutive b)
        uint32_t xr[32];
        #pragma unroll
        for (int j = 0; j < 32; j++)
            xr[j] = g_xbitsT[(ck * 32 + j) * BB + b];

        #pragma unroll
        for (int kw = 0; kw < 32; kw++) {
            const uint32_t xv = xr[kw];
            // broadcast vector loads: all lanes same address
            uint4 m0 = shm4[(ck * 32 + kw) * 8 + oset * 2];
            uint4 m1 = shm4[(ck * 32 + kw) * 8 + oset * 2 + 1];
            acc[0] += __popc(xv ^ m0.x);
            acc[1] += __popc(xv ^ m0.y);
            acc[2] += __popc(xv ^ m0.z);
            acc[3] += __popc(xv ^ m0.w);
            acc[4] += __popc(xv ^ m1.x);
            acc[5] += __popc(xv ^ m1.y);
            acc[6] += __popc(xv ^ m1.z);
            acc[7] += __popc(xv ^ m1.w);
        }
    }

    // ---------------- epilogue: threshold + float store ---------------------
    const int obase = o0 + oset * 8;
    float res[8];
    #pragma unroll
    for (int i = 0; i < 8; i++) {
        int cnt = KK - acc[i];                       // # equal bits (sum XNOR)
        res[i] = (cnt > thr[obase + i]) ? 1.0f : 0.0f;
    }
    float4* op = reinterpret_cast<float4*>(out + (size_t)b * OO + obase);
    op[0] = make_float4(res[0], res[1], res[2], res[3]);
    op[1] = make_float4(res[4], res[5], res[6], res[7]);
}

// ---------------------------------------------------------------------------
extern "C" void kernel_launch(void* const* d_in, const int* in_sizes, int n_in,
                              void* d_out, int out_size) {
    // Identify inputs by element count (robust to ordering)
    const void* x     = d_in[0];
    const void* masks = d_in[1];
    const int*  thr   = (const int*)d_in[2];
    for (int i = 0; i < n_in; i++) {
        if      (in_sizes[i] == KK * OO) masks = d_in[i];
        else if (in_sizes[i] == BB * KK) x     = d_in[i];
        else if (in_sizes[i] == OO)      thr   = (const int*)d_in[i];
    }

    pack_x_kernel<<<32, 256>>>((const uint32_t*)x);
    xnor_main_kernel<<<OO / OT, 256>>>((const uint32_t*)masks, thr, (float*)d_out);
}

// round 6
// speedup vs baseline: 1.0228x; 1.0228x over previous
#include <cuda_runtime.h>
#include <cstdint>

// Problem constants
#define BB 64      // batch
#define KK 4096    // dim_in
#define OO 4096    // dim_out
#define KW 128     // KK/32 bit-words along k
#define OT 16      // output columns per block (256 blocks)

// x bits, transposed for lane-coalesced reads in the main kernel: [kw][b]
__device__ uint32_t g_xbitsT[KW * BB];   // 32 KB

// Robust 0/1 extraction: works for int32 {0,1} (bit 0) and float32
// {0.0f,1.0f} (bit 23).
__device__ __forceinline__ uint32_t bit01(uint32_t w) {
    return (w | (w >> 23)) & 1u;
}

// ---------------------------------------------------------------------------
// Pack x (0/1 words) into bit-words. 8192 threads: one word each.
// Word (kw, b) holds bits k = kw*32 .. kw*32+31 of batch row b.
// ---------------------------------------------------------------------------
__global__ void pack_x_kernel(const uint32_t* __restrict__ x) {
    int t  = blockIdx.x * blockDim.x + threadIdx.x;   // 0..8191
    int kw = t >> 6;
    int b  = t & 63;
    const uint4* p = reinterpret_cast<const uint4*>(x + (size_t)b * KK + kw * 32);
    uint32_t w = 0;
    #pragma unroll
    for (int i = 0; i < 8; i++) {
        uint4 v = p[i];
        w |= bit01(v.x) << (4 * i);
        w |= bit01(v.y) << (4 * i + 1);
        w |= bit01(v.z) << (4 * i + 2);
        w |= bit01(v.w) << (4 * i + 3);
    }
    g_xbitsT[kw * BB + b] = w;
}

// ---------------------------------------------------------------------------
// Main kernel: 256 blocks x 256 threads, 16 output columns per block.
//   phase 1: read mask strip [4096 k][16 o] words, bit-pack into shared [kw][o]
//   phase 2: XNOR-popcount vs x bits (lanes = batch), fused threshold epilogue
// launch_bounds(256,2): cap regs so >=2 blocks co-reside per SM, letting one
// block's phase-1 DRAM stream overlap another's phase-2 compute.
// ---------------------------------------------------------------------------
__global__ void __launch_bounds__(256, 2) xnor_main_kernel(
    const uint32_t* __restrict__ masks,  // [KK][OO] 0/1 words
    const int*      __restrict__ thr,    // [OO] int32
    float*          __restrict__ out)    // [BB][OO] float32 0/1
{
    __shared__ uint32_t sh_m[KW * OT];   // 8 KB, layout [kw][o]

    const int t  = threadIdx.x;
    const int o0 = blockIdx.x * OT;

    // ---------------- phase 1: pack mask column strip into shared bits -----
    // thread -> (og = column quad 0..3, kwb = 0..63); handles kw = kwb + 64*r
    {
        const int og  = t & 3;
        const int kwb = t >> 2;
        #pragma unroll
        for (int r = 0; r < 2; r++) {
            const int kw = kwb + 64 * r;
            uint32_t a0 = 0, a1 = 0, a2 = 0, a3 = 0;
            const uint4* base = reinterpret_cast<const uint4*>(
                masks + (size_t)(kw * 32) * OO + o0 + og * 4);
            #pragma unroll
            for (int j = 0; j < 32; j++) {
                // row kw*32+j, columns o0+og*4 .. +3 (64B-aligned sectors)
                uint4 m = base[(size_t)j * (OO / 4)];
                a0 |= bit01(m.x) << j;
                a1 |= bit01(m.y) << j;
                a2 |= bit01(m.z) << j;
                a3 |= bit01(m.w) << j;
            }
            // sh_m[kw][4*og .. 4*og+3], 16B vector store
            reinterpret_cast<uint4*>(sh_m)[kw * 4 + og] = make_uint4(a0, a1, a2, a3);
        }
    }
    __syncthreads();

    // ---------------- phase 2: XNOR popcount main loop ----------------------
    const int lane = t & 31;
    const int warp = t >> 5;
    const int half = warp & 1;        // which 32 batches
    const int oset = warp >> 1;       // 0..3 -> 4 columns each
    const int b    = half * 32 + lane;

    int acc[4] = {0, 0, 0, 0};
    const uint4* shm4 = reinterpret_cast<const uint4*>(sh_m);

    #pragma unroll
    for (int ck = 0; ck < 16; ck++) {
        // x bit-words for this chunk, lane-coalesced (lanes = consecutive b)
        uint32_t xr[8];
        #pragma unroll
        for (int j = 0; j < 8; j++)
            xr[j] = g_xbitsT[(ck * 8 + j) * BB + b];

        #pragma unroll
        for (int j = 0; j < 8; j++) {
            const uint32_t xv = xr[j];
            // broadcast vector load: all lanes same address
            uint4 m = shm4[(ck * 8 + j) * 4 + oset];
            acc[0] += __popc(xv ^ m.x);
            acc[1] += __popc(xv ^ m.y);
            acc[2] += __popc(xv ^ m.z);
            acc[3] += __popc(xv ^ m.w);
        }
    }

    // ---------------- epilogue: threshold + float store ---------------------
    const int obase = o0 + oset * 4;
    float res[4];
    #pragma unroll
    for (int i = 0; i < 4; i++) {
        int cnt = KK - acc[i];                       // # equal bits (sum XNOR)
        res[i] = (cnt > thr[obase + i]) ? 1.0f : 0.0f;
    }
    *reinterpret_cast<float4*>(out + (size_t)b * OO + obase) =
        make_float4(res[0], res[1], res[2], res[3]);
}

// ---------------------------------------------------------------------------
extern "C" void kernel_launch(void* const* d_in, const int* in_sizes, int n_in,
                              void* d_out, int out_size) {
    // Identify inputs by element count (robust to ordering)
    const void* x     = d_in[0];
    const void* masks = d_in[1];
    const int*  thr   = (const int*)d_in[2];
    for (int i = 0; i < n_in; i++) {
        if      (in_sizes[i] == KK * OO) masks = d_in[i];
        else if (in_sizes[i] == BB * KK) x     = d_in[i];
        else if (in_sizes[i] == OO)      thr   = (const int*)d_in[i];
    }

    pack_x_kernel<<<32, 256>>>((const uint32_t*)x);
    xnor_main_kernel<<<OO / OT, 256>>>((const uint32_t*)masks, thr, (float*)d_out);
}